// round 11
// baseline (speedup 1.0000x reference)
#include <cuda_runtime.h>
#include <cuda_bf16.h>
#include <cstdint>
#include <math.h>

// Problem constants
#define NB 32      // batch
#define NS 2048    // sequence
#define NE 1024    // encoder hidden
#define NP 1024    // out dim (p)
#define FAN 2048   // attn_w row length

#define NROWS (NS * NB)           // 65536 flattened (s,b) rows
#define MT 64                     // rows per CTA  [R10: was 128 -> 2048 CTAs]
#define NHALF 512                 // p-cols per CTA (4 n-blocks) [back to R7 value]
#define NBLK 128                  // p-cols per n-block
#define KC 32                     // K chunk (bf16) = 64 bytes/row
#define NCH (NE / KC)             // 32 chunks

#define ATILE (MT * 64)           // 4096: 64 rows x 64B (swizzled, no pad)
#define BTILE (NBLK * 64)         // 8192: 128 rows x 64B
#define OA_HI 0
#define OA_LO ATILE               // 4096
#define OB_HI (2 * ATILE)         // 8192
#define OB_LO (2 * ATILE + BTILE) // 16384
#define BUFB  (2 * ATILE + 2 * BTILE)  // 24576 per stage
#define NSTAGE 3
#define SM_RED (NSTAGE * BUFB)    // 73728  (4 x 64 floats)
#define SM_DYN (SM_RED + 4 * MT * 4)   // 74752

// ---------------------------------------------------------------------------
// Scratch (device globals; no allocation allowed)
// ---------------------------------------------------------------------------
__device__ float g_hp[NB * NP];                       // h_proj + bias
__device__ float g_part[2 * NB * NS];                 // per p-half partial logits
__device__ float g_att[NB * NS];                      // softmax weights
__device__ float g_wpart[16 * NB * NE];               // per s-chunk partial weighted

__device__ __nv_bfloat16 g_enc_hi[(size_t)NS * NB * NE];   // 128 MB
__device__ __nv_bfloat16 g_enc_lo[(size_t)NS * NB * NE];   // 128 MB
__device__ __nv_bfloat16 g_w_hi[NP * NE];                  // 2 MB
__device__ __nv_bfloat16 g_w_lo[NP * NE];                  // 2 MB

// ---------------------------------------------------------------------------
// PTX helpers (sm_100-safe: ldmatrix + mma.sync + cp.async, NO tcgen05)
// ---------------------------------------------------------------------------
__device__ __forceinline__ uint32_t smem_u32(const void* p) {
    uint32_t a;
    asm("{ .reg .u64 t; cvta.to.shared.u64 t, %1; cvt.u32.u64 %0, t; }" : "=r"(a) : "l"(p));
    return a;
}
__device__ __forceinline__ void ldsm_x4(uint32_t* r, uint32_t addr) {
    asm volatile("ldmatrix.sync.aligned.m8n8.x4.shared.b16 {%0,%1,%2,%3}, [%4];"
                 : "=r"(r[0]), "=r"(r[1]), "=r"(r[2]), "=r"(r[3]) : "r"(addr));
}
__device__ __forceinline__ void mma16816(float* c,
                                         uint32_t a0, uint32_t a1, uint32_t a2, uint32_t a3,
                                         uint32_t b0, uint32_t b1) {
    asm volatile(
        "mma.sync.aligned.m16n8k16.row.col.f32.bf16.bf16.f32 "
        "{%0,%1,%2,%3}, {%4,%5,%6,%7}, {%8,%9}, {%0,%1,%2,%3};"
        : "+f"(c[0]), "+f"(c[1]), "+f"(c[2]), "+f"(c[3])
        : "r"(a0), "r"(a1), "r"(a2), "r"(a3), "r"(b0), "r"(b1));
}
__device__ __forceinline__ void cp16(uint32_t dst, const void* src) {
    asm volatile("cp.async.cg.shared.global [%0], [%1], 16;" :: "r"(dst), "l"(src));
}
#define CP_COMMIT() asm volatile("cp.async.commit_group;" ::: "memory")
#define CP_WAIT1()  asm volatile("cp.async.wait_group 1;" ::: "memory")

// Swizzled smem offset within a tile: row r, 16B segment seg (0..3).
__device__ __forceinline__ uint32_t swz(int r, int seg) {
    return (uint32_t)(r * 64 + (((seg) ^ ((r >> 1) & 3)) << 4));
}

// ---------------------------------------------------------------------------
// Kernel 1: hp[b,p] = hidden[b,:]·attn_w[p,0:1024] + attn_b[p]   (fp32 exact)
// ---------------------------------------------------------------------------
__global__ void __launch_bounds__(256) setup_kernel(
    const float* __restrict__ hidden,
    const float* __restrict__ attn_w,
    const float* __restrict__ attn_b)
{
    int p = blockIdx.x;
    int tid = threadIdx.x;
    int lane = tid & 31, wid = tid >> 5;

    __shared__ float ws[NE];
    __shared__ float warp_part[NB][8];

    for (int o = tid; o < NE; o += 256) ws[o] = attn_w[(size_t)p * FAN + o];
    __syncthreads();

    float acc[NB];
#pragma unroll
    for (int b = 0; b < NB; b++) acc[b] = 0.f;

    for (int o = tid; o < NE; o += 256) {
        float w = ws[o];
#pragma unroll
        for (int b = 0; b < NB; b++) acc[b] += hidden[b * NE + o] * w;
    }
#pragma unroll
    for (int b = 0; b < NB; b++) {
        float s = acc[b];
#pragma unroll
        for (int off = 16; off; off >>= 1) s += __shfl_down_sync(0xffffffffu, s, off);
        if (lane == 0) warp_part[b][wid] = s;
    }
    __syncthreads();
    if (tid < NB) {
        float s = 0.f;
#pragma unroll
        for (int w = 0; w < 8; w++) s += warp_part[tid][w];
        g_hp[tid * NP + p] = s + attn_b[p];
    }
}

// ---------------------------------------------------------------------------
// Conversion: fp32 -> (hi, lo) bf16 split
// ---------------------------------------------------------------------------
__device__ __forceinline__ void split4(float4 x, uint2& hi, uint2& lo) {
    __nv_bfloat16 h0 = __float2bfloat16_rn(x.x);
    __nv_bfloat16 h1 = __float2bfloat16_rn(x.y);
    __nv_bfloat16 h2 = __float2bfloat16_rn(x.z);
    __nv_bfloat16 h3 = __float2bfloat16_rn(x.w);
    __nv_bfloat16 l0 = __float2bfloat16_rn(x.x - __bfloat162float(h0));
    __nv_bfloat16 l1 = __float2bfloat16_rn(x.y - __bfloat162float(h1));
    __nv_bfloat16 l2 = __float2bfloat16_rn(x.z - __bfloat162float(h2));
    __nv_bfloat16 l3 = __float2bfloat16_rn(x.w - __bfloat162float(h3));
    hi.x = ((uint32_t)__bfloat16_as_ushort(h1) << 16) | __bfloat16_as_ushort(h0);
    hi.y = ((uint32_t)__bfloat16_as_ushort(h3) << 16) | __bfloat16_as_ushort(h2);
    lo.x = ((uint32_t)__bfloat16_as_ushort(l1) << 16) | __bfloat16_as_ushort(l0);
    lo.y = ((uint32_t)__bfloat16_as_ushort(l3) << 16) | __bfloat16_as_ushort(l2);
}

__global__ void __launch_bounds__(256) convert_enc_kernel(const float* __restrict__ enc)
{
    size_t i = (size_t)blockIdx.x * 256 + threadIdx.x;   // float4 index
    float4 x = ((const float4*)enc)[i];
    uint2 hi, lo;
    split4(x, hi, lo);
    ((uint2*)g_enc_hi)[i] = hi;
    ((uint2*)g_enc_lo)[i] = lo;
}

__global__ void __launch_bounds__(256) convert_w_kernel(const float* __restrict__ attn_w)
{
    int i = blockIdx.x * 256 + threadIdx.x;  // float4 index into w_e (256 per row)
    int p = i >> 8;
    int q = i & 255;
    float4 x = *(const float4*)(attn_w + (size_t)p * FAN + NE + q * 4);
    uint2 hi, lo;
    split4(x, hi, lo);
    ((uint2*)g_w_hi)[p * 256 + q] = hi;
    ((uint2*)g_w_lo)[p * 256 + q] = lo;
}

// ---------------------------------------------------------------------------
// Kernel 2 (dominant): split-bf16 HMMA energy GEMM, 3-stage cp.async pipeline,
// swizzled smem, fused tanh·v epilogue.
// CTA: 64 rows x 512 p (4 n-blocks of 128). 8 warps (2m x 4n), warp 32x32.
// Grid (1024, 2) = 2048 CTAs -> 6.9 waves on 296 concurrent (tail ~1%).
// ---------------------------------------------------------------------------
__global__ void __launch_bounds__(256, 2) energy_hmma_kernel(const float* __restrict__ v)
{
    extern __shared__ char smem[];
    const uint32_t su = smem_u32(smem);

    const int r0 = blockIdx.x * MT;          // global row base (s*32+b flat)
    const int ny = blockIdx.y;               // p half: 0 or 1
    const int tid = threadIdx.x;
    const int lane = tid & 31, wid = tid >> 5;
    const int wm = wid >> 2;                 // 0..1 (m, 32 rows each)
    const int wn = wid & 3;                  // 0..3 (n)

    // ldmatrix per-lane row constants
    const int grp = lane >> 3, lrow = lane & 7;
    uint32_t abase[2]; int arsw[2];
#pragma unroll
    for (int mt = 0; mt < 2; mt++) {
        int row = wm * 32 + mt * 16 + lrow + ((grp & 1) << 3);   // 0..63
        abase[mt] = (uint32_t)(row * 64);
        arsw[mt] = (row >> 1) & 3;
    }
    const int asg = grp >> 1;                // A column-half segment bit
    uint32_t bbase[2]; int brsw[2];
#pragma unroll
    for (int ntp = 0; ntp < 2; ntp++) {
        int row = wn * 32 + ntp * 16 + ((grp >> 1) << 3) + lrow; // 0..127
        bbase[ntp] = (uint32_t)(row * 64);
        brsw[ntp] = (row >> 1) & 3;
    }
    const int bsg = grp & 1;                 // B column-half segment bit

    const uint4* gAH = (const uint4*)g_enc_hi;
    const uint4* gAL = (const uint4*)g_enc_lo;
    const uint4* gBH = (const uint4*)g_w_hi;
    const uint4* gBL = (const uint4*)g_w_lo;

    float* sh_red = (float*)(smem + SM_RED);

    // staging constants: r1 in 0..63 covers A rows; r1 and r1+64 cover B rows
    const int r1 = tid >> 2, sg = tid & 3;
    const int r2 = r1 + 64;
    const uint32_t so1 = swz(r1, sg);
    const uint32_t so2 = swz(r2, sg);

    const int qr = lane >> 2, qc = lane & 3;
    float rowsum = 0.f;                      // valid for tid < MT

    for (int nb = 0; nb < NHALF / NBLK; nb++) {
        const int p0 = ny * NHALF + nb * NBLK;

        float acc[2][4][4];
#pragma unroll
        for (int mt = 0; mt < 2; mt++)
#pragma unroll
            for (int nt = 0; nt < 4; nt++)
#pragma unroll
                for (int e = 0; e < 4; e++) acc[mt][nt][e] = 0.f;

        auto stage = [&](int c) {
            const uint32_t bb = su + (uint32_t)(c % NSTAGE) * BUFB;
            const int cb = c * 4;   // uint4 offset along K
            cp16(bb + OA_HI + so1, gAH + (size_t)(r0 + r1) * 128 + cb + sg);
            cp16(bb + OA_LO + so1, gAL + (size_t)(r0 + r1) * 128 + cb + sg);
            cp16(bb + OB_HI + so1, gBH + (size_t)(p0 + r1) * 128 + cb + sg);
            cp16(bb + OB_HI + so2, gBH + (size_t)(p0 + r2) * 128 + cb + sg);
            cp16(bb + OB_LO + so1, gBL + (size_t)(p0 + r1) * 128 + cb + sg);
            cp16(bb + OB_LO + so2, gBL + (size_t)(p0 + r2) * 128 + cb + sg);
        };

        stage(0); CP_COMMIT();
        stage(1); CP_COMMIT();

        for (int c = 0; c < NCH; c++) {
            CP_WAIT1();                       // group c complete
            __syncthreads();                  // data visible; buf (c-1)%3 free
            if (c + 2 < NCH) stage(c + 2);    // writes buf (c-1)%3
            CP_COMMIT();

            const uint32_t base = su + (uint32_t)(c % NSTAGE) * BUFB;
#pragma unroll
            for (int ks = 0; ks < 2; ks++) {
                uint32_t bh[2][4], bl[2][4];
#pragma unroll
                for (int ntp = 0; ntp < 2; ntp++) {
                    const int seg = 2 * ks + bsg;
                    const uint32_t bo = bbase[ntp] + (uint32_t)((seg ^ brsw[ntp]) << 4);
                    ldsm_x4(bh[ntp], base + OB_HI + bo);
                    ldsm_x4(bl[ntp], base + OB_LO + bo);
                }
#pragma unroll
                for (int mt = 0; mt < 2; mt++) {
                    const int seg = 2 * ks + asg;
                    const uint32_t ao = abase[mt] + (uint32_t)((seg ^ arsw[mt]) << 4);
                    uint32_t ah[4], al[4];
                    ldsm_x4(ah, base + OA_HI + ao);
                    ldsm_x4(al, base + OA_LO + ao);
#pragma unroll
                    for (int ntp = 0; ntp < 2; ntp++) {
                        mma16816(acc[mt][2 * ntp],     ah[0], ah[1], ah[2], ah[3],
                                 bh[ntp][0], bh[ntp][1]);
                        mma16816(acc[mt][2 * ntp + 1], ah[0], ah[1], ah[2], ah[3],
                                 bh[ntp][2], bh[ntp][3]);
                        mma16816(acc[mt][2 * ntp],     al[0], al[1], al[2], al[3],
                                 bh[ntp][0], bh[ntp][1]);
                        mma16816(acc[mt][2 * ntp + 1], al[0], al[1], al[2], al[3],
                                 bh[ntp][2], bh[ntp][3]);
                        mma16816(acc[mt][2 * ntp],     ah[0], ah[1], ah[2], ah[3],
                                 bl[ntp][0], bl[ntp][1]);
                        mma16816(acc[mt][2 * ntp + 1], ah[0], ah[1], ah[2], ah[3],
                                 bl[ntp][2], bl[ntp][3]);
                    }
                }
            }
        }

        // Epilogue: rsum over 128 p of tanh(acc + hp)*v ; hp/v from gmem (L2)
#pragma unroll
        for (int mt = 0; mt < 2; mt++) {
            int row0 = wm * 32 + mt * 16 + qr;       // local row (0..63)
            int b0 = row0 & 31, b1 = (row0 + 8) & 31;
            float s0 = 0.f, s1 = 0.f;
#pragma unroll
            for (int nt = 0; nt < 4; nt++) {
                int pl = wn * 32 + nt * 8 + qc * 2;
                float2 v2  = *(const float2*)(v + p0 + pl);
                float2 h0c = *(const float2*)(g_hp + b0 * NP + p0 + pl);
                float2 h1c = *(const float2*)(g_hp + b1 * NP + p0 + pl);
                s0 += tanhf(acc[mt][nt][0] + h0c.x) * v2.x
                    + tanhf(acc[mt][nt][1] + h0c.y) * v2.y;
                s1 += tanhf(acc[mt][nt][2] + h1c.x) * v2.x
                    + tanhf(acc[mt][nt][3] + h1c.y) * v2.y;
            }
            s0 += __shfl_down_sync(0xffffffffu, s0, 2, 4);
            s0 += __shfl_down_sync(0xffffffffu, s0, 1, 4);
            s1 += __shfl_down_sync(0xffffffffu, s1, 2, 4);
            s1 += __shfl_down_sync(0xffffffffu, s1, 1, 4);
            if (qc == 0) {
                sh_red[wn * MT + row0]     = s0;
                sh_red[wn * MT + row0 + 8] = s1;
            }
        }
        __syncthreads();
        if (tid < MT)
            rowsum += sh_red[tid] + sh_red[MT + tid] + sh_red[2 * MT + tid]
                    + sh_red[3 * MT + tid];
        __syncthreads();   // sh_red safe to reuse next nb
    }

    if (tid < MT) {
        int grow = r0 + tid;
        int b = grow & 31;
        int s = grow >> 5;
        g_part[((size_t)ny * NB + b) * NS + s] = rowsum;
    }
}

// ---------------------------------------------------------------------------
// Kernel 3: logits = sum of 2 p-half partials; softmax over S per b.
// ---------------------------------------------------------------------------
__global__ void __launch_bounds__(256) softmax_kernel()
{
    int b = blockIdx.x;
    int tid = threadIdx.x;
    int lane = tid & 31, wid = tid >> 5;
    __shared__ float redm[8];
    __shared__ float reds[8];

    float vals[8];
    float m = -1e30f;
#pragma unroll
    for (int i = 0; i < 8; i++) {
        int s = tid + i * 256;
        float a = g_part[(size_t)b * NS + s] + g_part[((size_t)NB + b) * NS + s];
        vals[i] = a;
        m = fmaxf(m, a);
    }
#pragma unroll
    for (int off = 16; off; off >>= 1) m = fmaxf(m, __shfl_xor_sync(0xffffffffu, m, off));
    if (lane == 0) redm[wid] = m;
    __syncthreads();
    float bmax = redm[0];
#pragma unroll
    for (int w = 1; w < 8; w++) bmax = fmaxf(bmax, redm[w]);

    float ssum = 0.f;
#pragma unroll
    for (int i = 0; i < 8; i++) {
        vals[i] = expf(vals[i] - bmax);
        ssum += vals[i];
    }
#pragma unroll
    for (int off = 16; off; off >>= 1) ssum += __shfl_xor_sync(0xffffffffu, ssum, off);
    if (lane == 0) reds[wid] = ssum;
    __syncthreads();
    float tot = 0.f;
#pragma unroll
    for (int w = 0; w < 8; w++) tot += reds[w];
    float inv = 1.f / tot;

#pragma unroll
    for (int i = 0; i < 8; i++)
        g_att[b * NS + tid + i * 256] = vals[i] * inv;
}

// ---------------------------------------------------------------------------
// Kernel 4: weighted partials per (s-chunk of 128, b)
// ---------------------------------------------------------------------------
__global__ void __launch_bounds__(256) weighted_kernel(const float* __restrict__ enc)
{
    const int chunk = blockIdx.x;
    const int b = blockIdx.y;
    const int tid = threadIdx.x;

    __shared__ float aw[128];
    if (tid < 128) aw[tid] = g_att[b * NS + chunk * 128 + tid];
    __syncthreads();

    const float4* base = (const float4*)enc +
                         ((size_t)(chunk * 128) * NB + b) * (NE / 4) + tid;
    const size_t rowStride = (size_t)NB * NE / 4;

    float4 acc = make_float4(0.f, 0.f, 0.f, 0.f);
#pragma unroll 4
    for (int s = 0; s < 128; s++) {
        float w = aw[s];
        float4 x = base[(size_t)s * rowStride];
        acc.x += w * x.x; acc.y += w * x.y;
        acc.z += w * x.z; acc.w += w * x.w;
    }
    float4* o = (float4*)&g_wpart[((size_t)chunk * NB + b) * NE] + tid;
    *o = acc;
}

// ---------------------------------------------------------------------------
// Kernel 5: reduce 16 s-chunk partials -> out
// ---------------------------------------------------------------------------
__global__ void __launch_bounds__(256) reduce_kernel(float* __restrict__ out)
{
    int idx = blockIdx.x * 256 + threadIdx.x;
    float acc = 0.f;
#pragma unroll
    for (int c = 0; c < 16; c++)
        acc += g_wpart[(size_t)c * (NB * NE) + idx];
    out[idx] = acc;
}

// ---------------------------------------------------------------------------
extern "C" void kernel_launch(void* const* d_in, const int* in_sizes, int n_in,
                              void* d_out, int out_size)
{
    const float* hidden = (const float*)d_in[0];   // (32, 1024)
    const float* enc    = (const float*)d_in[1];   // (2048, 32, 1024)
    const float* attn_w = (const float*)d_in[2];   // (1024, 2048)
    const float* attn_b = (const float*)d_in[3];   // (1024,)
    const float* v      = (const float*)d_in[4];   // (1024,)
    float* out = (float*)d_out;                    // (32, 1024)

    cudaFuncSetAttribute(energy_hmma_kernel,
                         cudaFuncAttributeMaxDynamicSharedMemorySize, SM_DYN);

    setup_kernel<<<NP, 256>>>(hidden, attn_w, attn_b);
    convert_w_kernel<<<(NP * NE / 4) / 256, 256>>>(attn_w);
    convert_enc_kernel<<<(int)(((size_t)NS * NB * NE / 4) / 256), 256>>>(enc);
    energy_hmma_kernel<<<dim3(NROWS / MT, 2), 256, SM_DYN>>>(v);
    softmax_kernel<<<NB, 256>>>();
    weighted_kernel<<<dim3(16, NB), 256>>>(enc);
    reduce_kernel<<<(NB * NE) / 256, 256>>>(out);
}